// round 5
// baseline (speedup 1.0000x reference)
#include <cuda_runtime.h>

// RotaryEmbedding: x (4,16,8192,64) fp32. Rotate first 4 pairs (elems 0..7)
// of each 64-float row; copy the remaining 56 floats unchanged.
//
// R4 lessons: __ldcs/__stcs REGRESSED (they defeat cross-replay L2 retention;
// apparent BW 7.6 TB/s > LTS ceiling proves L2 hits matter here). Reverted.
// R3 lesson: CHUNKS=8 best MLP but regs=54 capped occ at 41%.
// R5: plain loads/stores, exact cover, __launch_bounds__(256,6) to cap regs
// ~42 (8 float4 = 32 data regs + base pointers; load offsets are immediates)
// -> 6 blocks/SM, occ ~75%, keeping MLP_p1=8.

#define CHUNKS 8
#define TPB 256

__device__ __forceinline__ void rope_math(float4 v[CHUNKS], int col4,
                                          const float* __restrict__ dparam,
                                          const float* __restrict__ thetas)
{
    if (col4 < 2) {
        // direction = sigmoid(d)*2 - 1 = tanh(d/2)
        float d = tanhf(0.5f * dparam[0]);
        int p = col4 * 2;
        float s0, c0, s1, c1;
        sincosf(d * thetas[p],     &s0, &c0);
        sincosf(d * thetas[p + 1], &s1, &c1);
        #pragma unroll
        for (int k = 0; k < CHUNKS; k++) {
            float xi0 = v[k].x, xj0 = v[k].y;
            float xi1 = v[k].z, xj1 = v[k].w;
            v[k].x =  xi0 * c0 + xj0 * s0;
            v[k].y = -xi0 * s0 + xj0 * c0;
            v[k].z =  xi1 * c1 + xj1 * s1;
            v[k].w = -xi1 * s1 + xj1 * c1;
        }
    }
}

// Fast path: grid covers n4 exactly, no guards.
__global__ __launch_bounds__(TPB, 6) void rope8_exact(
    const float4* __restrict__ x,
    const float*  __restrict__ dparam,
    const float*  __restrict__ thetas,
    float4*       __restrict__ out)
{
    int base = blockIdx.x * (TPB * CHUNKS) + threadIdx.x;

    float4 v[CHUNKS];
    #pragma unroll
    for (int k = 0; k < CHUNKS; k++)
        v[k] = x[base + k * TPB];

    rope_math(v, base & 15, dparam, thetas);

    #pragma unroll
    for (int k = 0; k < CHUNKS; k++)
        out[base + k * TPB] = v[k];
}

// Guarded fallback (not taken for the bench shape).
__global__ __launch_bounds__(TPB) void rope8_guarded(
    const float4* __restrict__ x,
    const float*  __restrict__ dparam,
    const float*  __restrict__ thetas,
    float4*       __restrict__ out,
    int n4)
{
    int base = blockIdx.x * (TPB * CHUNKS) + threadIdx.x;

    float4 v[CHUNKS];
    #pragma unroll
    for (int k = 0; k < CHUNKS; k++) {
        int i = base + k * TPB;
        if (i < n4) v[k] = x[i];
    }

    rope_math(v, base & 15, dparam, thetas);

    #pragma unroll
    for (int k = 0; k < CHUNKS; k++) {
        int i = base + k * TPB;
        if (i < n4) out[i] = v[k];
    }
}

extern "C" void kernel_launch(void* const* d_in, const int* in_sizes, int n_in,
                              void* d_out, int out_size)
{
    const float4* x      = (const float4*)d_in[0];
    const float*  dparam = (const float*)d_in[1];
    const float*  thetas = (const float*)d_in[2];
    float4*       out    = (float4*)d_out;

    int n4 = in_sizes[0] / 4;                   // 8,388,608 float4 chunks
    const int per_block = TPB * CHUNKS;         // 2048
    if (n4 % per_block == 0) {
        rope8_exact<<<n4 / per_block, TPB>>>(x, dparam, thetas, out);
    } else {
        int blocks = (n4 + per_block - 1) / per_block;
        rope8_guarded<<<blocks, TPB>>>(x, dparam, thetas, out, n4);
    }
}

// round 6
// speedup vs baseline: 1.0947x; 1.0947x over previous
#include <cuda_runtime.h>

// RotaryEmbedding: x (4,16,8192,64) fp32. Rotate first 4 pairs (elems 0..7)
// of each 64-float row; copy the remaining 56 floats unchanged.
//
// Evidence so far:
//  R3 (plain ld/st, CHUNKS=8, regs 54, occ 41%): hot 35.3us  <- best
//  R4 (.cs on loads AND stores): 37.3us — evict-first LOADS kill the
//      cross-replay L2 retention of the 134MB input (vs 126MB L2).
//  R5 (reg cap 40): 48us — ptxas spilled/serialized the 8-load batch
//      (L1% jumped to 57): MLP_p1 > occupancy for this kernel. Never cap regs.
//
// R6: R3 config + __stcs on STORES ONLY. Output is write-once-never-read;
// evict-first stores stop the 134MB write stream from displacing the input
// in L2, raising next-replay load hit rate.

#define CHUNKS 8
#define TPB 256

__device__ __forceinline__ void rope_math(float4 v[CHUNKS], int col4,
                                          const float* __restrict__ dparam,
                                          const float* __restrict__ thetas)
{
    if (col4 < 2) {
        // direction = sigmoid(d)*2 - 1 = tanh(d/2)
        float d = tanhf(0.5f * dparam[0]);
        int p = col4 * 2;
        float s0, c0, s1, c1;
        sincosf(d * thetas[p],     &s0, &c0);
        sincosf(d * thetas[p + 1], &s1, &c1);
        #pragma unroll
        for (int k = 0; k < CHUNKS; k++) {
            float xi0 = v[k].x, xj0 = v[k].y;
            float xi1 = v[k].z, xj1 = v[k].w;
            v[k].x =  xi0 * c0 + xj0 * s0;
            v[k].y = -xi0 * s0 + xj0 * c0;
            v[k].z =  xi1 * c1 + xj1 * s1;
            v[k].w = -xi1 * s1 + xj1 * c1;
        }
    }
}

// Fast path: grid covers n4 exactly, no guards.
__global__ __launch_bounds__(TPB) void rope8_exact(
    const float4* __restrict__ x,
    const float*  __restrict__ dparam,
    const float*  __restrict__ thetas,
    float4*       __restrict__ out)
{
    int base = blockIdx.x * (TPB * CHUNKS) + threadIdx.x;

    float4 v[CHUNKS];
    #pragma unroll
    for (int k = 0; k < CHUNKS; k++)
        v[k] = x[base + k * TPB];          // default load: keep input in L2

    rope_math(v, base & 15, dparam, thetas);

    #pragma unroll
    for (int k = 0; k < CHUNKS; k++)
        __stcs(&out[base + k * TPB], v[k]); // evict-first store: never read back

    // (guard-free: dispatch guarantees exact cover)
}

// Guarded fallback (not taken for the bench shape).
__global__ __launch_bounds__(TPB) void rope8_guarded(
    const float4* __restrict__ x,
    const float*  __restrict__ dparam,
    const float*  __restrict__ thetas,
    float4*       __restrict__ out,
    int n4)
{
    int base = blockIdx.x * (TPB * CHUNKS) + threadIdx.x;

    float4 v[CHUNKS];
    #pragma unroll
    for (int k = 0; k < CHUNKS; k++) {
        int i = base + k * TPB;
        if (i < n4) v[k] = x[i];
    }

    rope_math(v, base & 15, dparam, thetas);

    #pragma unroll
    for (int k = 0; k < CHUNKS; k++) {
        int i = base + k * TPB;
        if (i < n4) __stcs(&out[i], v[k]);
    }
}

extern "C" void kernel_launch(void* const* d_in, const int* in_sizes, int n_in,
                              void* d_out, int out_size)
{
    const float4* x      = (const float4*)d_in[0];
    const float*  dparam = (const float*)d_in[1];
    const float*  thetas = (const float*)d_in[2];
    float4*       out    = (float4*)d_out;

    int n4 = in_sizes[0] / 4;                   // 8,388,608 float4 chunks
    const int per_block = TPB * CHUNKS;         // 2048
    if (n4 % per_block == 0) {
        rope8_exact<<<n4 / per_block, TPB>>>(x, dparam, thetas, out);
    } else {
        int blocks = (n4 + per_block - 1) / per_block;
        rope8_guarded<<<blocks, TPB>>>(x, dparam, thetas, out, n4);
    }
}

// round 7
// speedup vs baseline: 1.1071x; 1.0113x over previous
#include <cuda_runtime.h>

// RotaryEmbedding: x (4,16,8192,64) fp32. Rotate first 4 pairs (elems 0..7)
// of each 64-float row; copy the remaining 56 floats unchanged.
//
// Evidence log:
//  R3 plain ld/st CHUNKS=8 TPB=256 (regs 54, occ 42%): hot 35.3us <- prev best
//  R4 .cs loads+stores: 37.3us (evict-first loads kill cross-replay L2 hits)
//  R5 reg cap 40: 48.0us (spills; MLP_p1 > occupancy, never cap regs)
//  R6 .cs stores only: 37.9us (ALL cache hints lose; default policy optimal)
//
// Model: load-latency-limited. Need ~7KB reads in flight/SM for 3TB/s read
// stream at ~600cyc; R3 had only ~3.4KB (27 warps x 8 ldg). R7: CHUNKS=16,
// TPB=128 -> ~20 warps x 16 ldg = 5.1KB in flight (+50%). No reg cap.

#define CHUNKS 16
#define TPB 128

__device__ __forceinline__ void rope_math(float4 v[CHUNKS], int col4,
                                          const float* __restrict__ dparam,
                                          const float* __restrict__ thetas)
{
    if (col4 < 2) {
        // direction = sigmoid(d)*2 - 1 = tanh(d/2)
        float d = tanhf(0.5f * dparam[0]);
        int p = col4 * 2;
        float s0, c0, s1, c1;
        sincosf(d * thetas[p],     &s0, &c0);
        sincosf(d * thetas[p + 1], &s1, &c1);
        #pragma unroll
        for (int k = 0; k < CHUNKS; k++) {
            float xi0 = v[k].x, xj0 = v[k].y;
            float xi1 = v[k].z, xj1 = v[k].w;
            v[k].x =  xi0 * c0 + xj0 * s0;
            v[k].y = -xi0 * s0 + xj0 * c0;
            v[k].z =  xi1 * c1 + xj1 * s1;
            v[k].w = -xi1 * s1 + xj1 * c1;
        }
    }
}

// Fast path: grid covers n4 exactly, no guards.
__global__ __launch_bounds__(TPB) void rope16_exact(
    const float4* __restrict__ x,
    const float*  __restrict__ dparam,
    const float*  __restrict__ thetas,
    float4*       __restrict__ out)
{
    int base = blockIdx.x * (TPB * CHUNKS) + threadIdx.x;

    float4 v[CHUNKS];
    #pragma unroll
    for (int k = 0; k < CHUNKS; k++)
        v[k] = x[base + k * TPB];

    rope_math(v, base & 15, dparam, thetas);   // TPB=128: stride preserves col4

    #pragma unroll
    for (int k = 0; k < CHUNKS; k++)
        out[base + k * TPB] = v[k];
}

// Guarded fallback (not taken for the bench shape).
__global__ __launch_bounds__(TPB) void rope16_guarded(
    const float4* __restrict__ x,
    const float*  __restrict__ dparam,
    const float*  __restrict__ thetas,
    float4*       __restrict__ out,
    int n4)
{
    int base = blockIdx.x * (TPB * CHUNKS) + threadIdx.x;

    float4 v[CHUNKS];
    #pragma unroll
    for (int k = 0; k < CHUNKS; k++) {
        int i = base + k * TPB;
        if (i < n4) v[k] = x[i];
    }

    rope_math(v, base & 15, dparam, thetas);

    #pragma unroll
    for (int k = 0; k < CHUNKS; k++) {
        int i = base + k * TPB;
        if (i < n4) out[i] = v[k];
    }
}

extern "C" void kernel_launch(void* const* d_in, const int* in_sizes, int n_in,
                              void* d_out, int out_size)
{
    const float4* x      = (const float4*)d_in[0];
    const float*  dparam = (const float*)d_in[1];
    const float*  thetas = (const float*)d_in[2];
    float4*       out    = (float4*)d_out;

    int n4 = in_sizes[0] / 4;                   // 8,388,608 float4 chunks
    const int per_block = TPB * CHUNKS;         // 2048
    if (n4 % per_block == 0) {
        rope16_exact<<<n4 / per_block, TPB>>>(x, dparam, thetas, out);
    } else {
        int blocks = (n4 + per_block - 1) / per_block;
        rope16_guarded<<<blocks, TPB>>>(x, dparam, thetas, out, n4);
    }
}

// round 8
// speedup vs baseline: 1.1411x; 1.0307x over previous
#include <cuda_runtime.h>
#include <cstdint>

// RotaryEmbedding: x (4,16,8192,64) fp32. Rotate first 4 pairs (elems 0..7)
// of each 64-float row (256B); copy the remaining 224B unchanged.
//
// Evidence log:
//  R3 LDG/STG CHUNKS=8:  hot 35.3us, DRAM 75.9%  <- best register-path
//  R4/R6 cache hints:    regress (default L2 policy optimal)
//  R5 reg cap:           regress (spills; never cap regs)
//  R7 CHUNKS=16:         occ fell so in-flight loads UNCHANGED (~214/SM).
//     -> register file caps in-flight bytes at ~3.4KB/SM; need ~7KB to cover
//        DRAM latency. LDG/STG design exhausted.
//
// R8: TMA bulk staging. Each CTA: cp.async.bulk 16KB g->s (1 instr),
// rotate 64 rows x 32B in SMEM (copy bytes never touch RF), fence,
// cp.async.bulk 16KB s->g. ~13 CTAs/SM x 16KB = >100KB in flight per SM.

#define TILE_BYTES   16384              // 64 rows x 256 B
#define ROWS_PER_TILE 64
#define TPB 128                          // 64 rows x 2 rotating float4s

__device__ __forceinline__ uint32_t smem_u32(const void* p) {
    uint32_t a;
    asm("{ .reg .u64 t; cvta.to.shared.u64 t, %1; cvt.u32.u64 %0, t; }"
        : "=r"(a) : "l"(p));
    return a;
}

__global__ __launch_bounds__(TPB) void rope_tma_kernel(
    const char* __restrict__ x,
    const float* __restrict__ dparam,
    const float* __restrict__ thetas,
    char* __restrict__ out)
{
    __shared__ __align__(128) float tile[TILE_BYTES / 4];
    __shared__ __align__(8) uint64_t mbar;

    const int tid = threadIdx.x;
    const size_t tile_off = (size_t)blockIdx.x * TILE_BYTES;
    const uint32_t s_tile = smem_u32(tile);
    const uint32_t s_mbar = smem_u32(&mbar);

    if (tid == 0) {
        asm volatile("mbarrier.init.shared.b64 [%0], 1;" :: "r"(s_mbar) : "memory");
    }
    __syncthreads();

    if (tid == 0) {
        asm volatile("mbarrier.arrive.expect_tx.shared.b64 _, [%0], %1;"
                     :: "r"(s_mbar), "r"((uint32_t)TILE_BYTES) : "memory");
        asm volatile("cp.async.bulk.shared::cta.global.mbarrier::complete_tx::bytes "
                     "[%0], [%1], %2, [%3];"
                     :: "r"(s_tile), "l"(x + tile_off),
                        "r"((uint32_t)TILE_BYTES), "r"(s_mbar) : "memory");
    }

    // Coefficients — overlapped with the TMA load.
    // thread t handles row = t>>1, chunk c = t&1 (floats 4c..4c+3 of that row)
    const int c = tid & 1;
    const int row = tid >> 1;
    const float d = tanhf(0.5f * dparam[0]);   // sigmoid(d)*2-1
    float s0, c0, s1, c1;
    sincosf(d * thetas[2 * c],     &s0, &c0);
    sincosf(d * thetas[2 * c + 1], &s1, &c1);

    // Wait for tile arrival (phase 0)
    {
        uint32_t done;
        asm volatile(
            "{\n\t.reg .pred p;\n\t"
            "mbarrier.try_wait.parity.acquire.cta.shared::cta.b64 p, [%1], 0;\n\t"
            "selp.b32 %0, 1, 0, p;\n\t}"
            : "=r"(done) : "r"(s_mbar) : "memory");
        while (!done) {
            asm volatile(
                "{\n\t.reg .pred p;\n\t"
                "mbarrier.try_wait.parity.acquire.cta.shared::cta.b64 p, [%1], 0, 0x989680;\n\t"
                "selp.b32 %0, 1, 0, p;\n\t}"
                : "=r"(done) : "r"(s_mbar) : "memory");
        }
    }

    // Rotate in SMEM: float4 at row*64 + c*4
    {
        float4* p = reinterpret_cast<float4*>(&tile[row * 64 + c * 4]);
        float4 v = *p;
        float xi0 = v.x, xj0 = v.y, xi1 = v.z, xj1 = v.w;
        v.x =  xi0 * c0 + xj0 * s0;
        v.y = -xi0 * s0 + xj0 * c0;
        v.z =  xi1 * c1 + xj1 * s1;
        v.w = -xi1 * s1 + xj1 * c1;
        *p = v;
    }
    __syncthreads();

    if (tid == 0) {
        asm volatile("fence.proxy.async.shared::cta;" ::: "memory");
        asm volatile("cp.async.bulk.global.shared::cta.bulk_group [%0], [%1], %2;"
                     :: "l"(out + tile_off), "r"(s_tile),
                        "r"((uint32_t)TILE_BYTES) : "memory");
        asm volatile("cp.async.bulk.commit_group;" ::: "memory");
        asm volatile("cp.async.bulk.wait_group 0;" ::: "memory");
    }
}

// ---------- Guarded fallback (register path, not taken for bench shape) ----------
#define CHUNKS 8
#define FTPB 256

__global__ __launch_bounds__(FTPB) void rope8_guarded(
    const float4* __restrict__ x,
    const float*  __restrict__ dparam,
    const float*  __restrict__ thetas,
    float4*       __restrict__ out,
    int n4)
{
    int base = blockIdx.x * (FTPB * CHUNKS) + threadIdx.x;

    float4 v[CHUNKS];
    #pragma unroll
    for (int k = 0; k < CHUNKS; k++) {
        int i = base + k * FTPB;
        if (i < n4) v[k] = x[i];
    }

    int col4 = base & 15;
    if (col4 < 2) {
        float d = tanhf(0.5f * dparam[0]);
        int p = col4 * 2;
        float s0, c0, s1, c1;
        sincosf(d * thetas[p],     &s0, &c0);
        sincosf(d * thetas[p + 1], &s1, &c1);
        #pragma unroll
        for (int k = 0; k < CHUNKS; k++) {
            float xi0 = v[k].x, xj0 = v[k].y;
            float xi1 = v[k].z, xj1 = v[k].w;
            v[k].x =  xi0 * c0 + xj0 * s0;
            v[k].y = -xi0 * s0 + xj0 * c0;
            v[k].z =  xi1 * c1 + xj1 * s1;
            v[k].w = -xi1 * s1 + xj1 * c1;
        }
    }

    #pragma unroll
    for (int k = 0; k < CHUNKS; k++) {
        int i = base + k * FTPB;
        if (i < n4) out[i] = v[k];
    }
}

extern "C" void kernel_launch(void* const* d_in, const int* in_sizes, int n_in,
                              void* d_out, int out_size)
{
    const float*  xf     = (const float*)d_in[0];
    const float*  dparam = (const float*)d_in[1];
    const float*  thetas = (const float*)d_in[2];

    long long nbytes = (long long)in_sizes[0] * 4;
    if (nbytes % TILE_BYTES == 0) {
        int tiles = (int)(nbytes / TILE_BYTES);     // 8192
        rope_tma_kernel<<<tiles, TPB>>>((const char*)xf, dparam, thetas,
                                        (char*)d_out);
    } else {
        int n4 = in_sizes[0] / 4;
        int blocks = (n4 + FTPB * CHUNKS - 1) / (FTPB * CHUNKS);
        rope8_guarded<<<blocks, FTPB>>>((const float4*)xf, dparam, thetas,
                                        (float4*)d_out, n4);
    }
}